// round 1
// baseline (speedup 1.0000x reference)
#include <cuda_runtime.h>
#include <math.h>

// Problem constants
#define NB   2048     // batches
#define BPB  4        // batches per block
#define NGRID (NB / BPB)
#define HID  64
#define TAU  22
#define ALPHA_LRELU 0.2f

struct Smem {
    float W1[2][7][HID];   // u/d att weights (7x64 each)
    float C1[2][7];        // W1 @ a[:64]   (source logit coeffs)
    float C2[2][7];        // W1 @ a[64:]   (target logit coeffs)
    float T[256];          // per-node masked leaky logits e_j
    float X0[2][7];        // center-node features
    float S[2];            // center source logit
    float M[2];            // softmax max
    float Zi[2];           // softmax 1/Z
    float Ypart[8][7];     // per-warp partial of sum alpha_j * x_j
    float Y[2][7];         // sum alpha_j * x_j per graph
    float Wv[BPB][2][HID]; // elu(leaf) + 127*elu(center) per batch/graph
    float G[BPB][HID];     // u_g + d_g per batch
};

__device__ __forceinline__ float eluf(float x) { return x > 0.0f ? x : expm1f(x); }

__global__ void __launch_bounds__(256, 4) gat_star_kernel(
    const float* __restrict__ fp,
    const float* __restrict__ uW1, const float* __restrict__ uA,
    const float* __restrict__ uW2,
    const float* __restrict__ dW1, const float* __restrict__ dA,
    const float* __restrict__ dW2,
    const float* __restrict__ fc2W, const float* __restrict__ fc2b,
    float* __restrict__ out)
{
    __shared__ Smem sm;
    const int tid = threadIdx.x;

    // ---- stage weights ----
    for (int i = tid; i < 7 * HID; i += 256) {
        ((float*)sm.W1)[i]           = uW1[i];
        ((float*)sm.W1)[7 * HID + i] = dW1[i];
    }
    __syncthreads();
    // C1[g][f] = sum_k W1[g][f][k]*a[k];  C2 with a[64:]
    if (tid < 28) {
        int g = tid / 14, rem = tid % 14;
        int which = rem / 7, f = rem % 7;
        const float* a = (g == 0 ? uA : dA) + which * HID;
        float acc = 0.0f;
        #pragma unroll
        for (int k = 0; k < HID; k++) acc = fmaf(sm.W1[g][f][k], a[k], acc);
        if (which == 0) sm.C1[g][f] = acc; else sm.C2[g][f] = acc;
    }
    __syncthreads();

    const int g    = tid >> 7;   // graph: 0 = up, 1 = down
    const int j    = tid & 127;  // node within graph
    const int w    = tid >> 5;   // warp id (0..7)
    const int lane = tid & 31;

    for (int bb = 0; bb < BPB; bb++) {
        const long long bidx = (long long)blockIdx.x * BPB + bb;
        const float* xr = fp + (bidx * 256 + tid) * 10;
        float x[7];
        #pragma unroll
        for (int f = 0; f < 7; f++) x[f] = __ldg(&xr[f]);

        // attention logits: t_j = x_j . C2 ;  s_j = x_j . C1 (only node 0's used)
        float t = 0.0f, s = 0.0f;
        #pragma unroll
        for (int f = 0; f < 7; f++) {
            t = fmaf(x[f], sm.C2[g][f], t);
            s = fmaf(x[f], sm.C1[g][f], s);
        }
        if (j == 0) {
            sm.S[g] = s;
            #pragma unroll
            for (int f = 0; f < 7; f++) sm.X0[g][f] = x[f];
        }
        __syncthreads();

        // e_j = leaky_relu(s_0 + t_j), mask node 0
        float e = sm.S[g] + t;
        e = e > 0.0f ? e : ALPHA_LRELU * e;
        if (j == 0) e = -1e30f;
        sm.T[tid] = e;
        __syncthreads();

        // softmax reduce: warp 0 -> graph 0, warp 1 -> graph 1
        if (tid < 64) {
            int gg = tid >> 5, l2 = tid & 31;
            const float* Eg = &sm.T[gg * 128];
            float v0 = Eg[l2], v1 = Eg[l2 + 32], v2 = Eg[l2 + 64], v3 = Eg[l2 + 96];
            float m = fmaxf(fmaxf(v0, v1), fmaxf(v2, v3));
            #pragma unroll
            for (int o = 16; o; o >>= 1) m = fmaxf(m, __shfl_xor_sync(0xffffffffu, m, o));
            float z = __expf(v0 - m) + __expf(v1 - m) + __expf(v2 - m) + __expf(v3 - m);
            #pragma unroll
            for (int o = 16; o; o >>= 1) z += __shfl_xor_sync(0xffffffffu, z, o);
            if (l2 == 0) { sm.M[gg] = m; sm.Zi[gg] = 1.0f / z; }
        }
        __syncthreads();

        float alpha = (j == 0) ? 0.0f : __expf(e - sm.M[g]) * sm.Zi[g];

        // Y[g][f] = sum_j alpha_j * x_j[f]  (warp shfl reduce, then combine)
        #pragma unroll
        for (int f = 0; f < 7; f++) {
            float v = alpha * x[f];
            #pragma unroll
            for (int o = 16; o; o >>= 1) v += __shfl_xor_sync(0xffffffffu, v, o);
            if (lane == 0) sm.Ypart[w][f] = v;
        }
        __syncthreads();
        if (tid < 14) {
            int gg = tid / 7, f = tid % 7;
            sm.Y[gg][f] = sm.Ypart[gg * 4][f] + sm.Ypart[gg * 4 + 1][f]
                        + sm.Ypart[gg * 4 + 2][f] + sm.Ypart[gg * 4 + 3][f];
        }
        __syncthreads();

        // Wv = elu(x0 @ W1) + 127 * elu(Y @ W1)
        if (tid < 128) {
            int gg = tid >> 6, k = tid & 63;
            float c = 0.0f, l = 0.0f;
            #pragma unroll
            for (int f = 0; f < 7; f++) {
                float w1 = sm.W1[gg][f][k];
                c = fmaf(sm.Y[gg][f],  w1, c);
                l = fmaf(sm.X0[gg][f], w1, l);
            }
            sm.Wv[bb][gg][k] = eluf(l) + 127.0f * eluf(c);
        }
        __syncthreads();
    }

    // ---- stage B: G[b][m] = sum_k uW2[k][m]*Wv[b][0][k] + dW2[k][m]*Wv[b][1][k]
    {
        int m = tid & 63;
        int b = tid >> 6;   // 0..3
        float acc = 0.0f;
        #pragma unroll 4
        for (int k = 0; k < HID; k++) {
            float wu = __ldg(&uW2[k * HID + m]);
            float wd = __ldg(&dW2[k * HID + m]);
            acc = fmaf(wu, sm.Wv[b][0][k], acc);
            acc = fmaf(wd, sm.Wv[b][1][k], acc);
        }
        sm.G[b][m] = acc;
    }
    __syncthreads();

    // ---- stage C: out = clip(relu(G @ fc2W + b), 0, 10)
    if (tid < BPB * TAU) {
        int b = tid / TAU, t = tid - b * TAU;
        float acc = __ldg(&fc2b[t]);
        #pragma unroll 4
        for (int m = 0; m < HID; m++)
            acc = fmaf(sm.G[b][m], __ldg(&fc2W[m * TAU + t]), acc);
        acc = fminf(fmaxf(acc, 0.0f), 10.0f);
        out[((long long)blockIdx.x * BPB + b) * TAU + t] = acc;
    }
}

extern "C" void kernel_launch(void* const* d_in, const int* in_sizes, int n_in,
                              void* d_out, int out_size)
{
    const float* fp    = (const float*)d_in[0];
    const float* uW1   = (const float*)d_in[1];
    const float* uA    = (const float*)d_in[2];
    const float* uW2   = (const float*)d_in[3];
    // d_in[4] = u_out_a : provably unused (singleton/uniform softmax in layer 2)
    const float* dW1   = (const float*)d_in[5];
    const float* dA    = (const float*)d_in[6];
    const float* dW2   = (const float*)d_in[7];
    // d_in[8] = d_out_a : unused
    const float* fc2W  = (const float*)d_in[9];
    const float* fc2b  = (const float*)d_in[10];
    float* out = (float*)d_out;

    gat_star_kernel<<<NGRID, 256>>>(fp, uW1, uA, uW2, dW1, dA, dW2, fc2W, fc2b, out);
}

// round 2
// speedup vs baseline: 1.1036x; 1.1036x over previous
#include <cuda_runtime.h>
#include <math.h>

#define NB   2048
#define BPB  4
#define NGRID (NB / BPB)
#define HID  64
#define TAU  22

struct Smem {
    float W1[2][7][HID];    // u/d layer-1 weights
    float C1[2][7];         // W1 @ a[:64]  (source coeffs)
    float C2[2][7];         // W1 @ a[64:]  (target coeffs)
    float Mp[BPB][8];       // per-warp softmax max
    float Zp[BPB][8];       // per-warp softmax partial Z
    float Yp[BPB][8][7];    // per-warp partial sum p_j * x_j
    float X0[BPB][2][7];    // center-node features
    float Y[BPB][2][7];     // normalized sum alpha_j x_j
    float Wv[BPB][2][HID];  // elu(center h1) + 127*elu(leaf h1)
    float G[BPB][HID];      // u_g + d_g
};

__device__ __forceinline__ float eluf(float x) { return x > 0.0f ? x : expm1f(x); }

__global__ void __launch_bounds__(256, 4) gat_star_kernel(
    const float* __restrict__ fp,
    const float* __restrict__ uW1, const float* __restrict__ uA,
    const float* __restrict__ uW2,
    const float* __restrict__ dW1, const float* __restrict__ dA,
    const float* __restrict__ dW2,
    const float* __restrict__ fc2W, const float* __restrict__ fc2b,
    float* __restrict__ out)
{
    __shared__ Smem sm;
    const int tid = threadIdx.x;

    // ---- stage weights + logit coefficient vectors ----
    for (int i = tid; i < 7 * HID; i += 256) {
        ((float*)sm.W1)[i]           = uW1[i];
        ((float*)sm.W1)[7 * HID + i] = dW1[i];
    }
    __syncthreads();
    if (tid < 28) {
        int g = tid / 14, rem = tid % 14;
        int which = rem / 7, f = rem % 7;
        const float* a = (g == 0 ? uA : dA) + which * HID;
        float acc = 0.0f;
        #pragma unroll
        for (int k = 0; k < HID; k++) acc = fmaf(sm.W1[g][f][k], a[k], acc);
        if (which == 0) sm.C1[g][f] = acc; else sm.C2[g][f] = acc;
    }
    __syncthreads();

    const int g    = tid >> 7;   // graph: 0 = up, 1 = down (warp-uniform)
    const int j    = tid & 127;  // node within graph
    const int w    = tid >> 5;   // warp id 0..7
    const int lane = tid & 31;

    const long long base = (long long)blockIdx.x * BPB * 2560;  // floats

    // ---- phase A: load all 4 batches' rows (vectorized, high MLP) ----
    float x[BPB][7];
    #pragma unroll
    for (int bb = 0; bb < BPB; bb++) {
        const float* r = fp + base + bb * 2560 + tid * 10;
        float2 p0 = *(const float2*)(r);
        float2 p1 = *(const float2*)(r + 2);
        float2 p2 = *(const float2*)(r + 4);
        x[bb][0] = p0.x; x[bb][1] = p0.y;
        x[bb][2] = p1.x; x[bb][3] = p1.y;
        x[bb][4] = p2.x; x[bb][5] = p2.y;
        x[bb][6] = __ldg(r + 6);
    }

    // center-node source logit s0 per batch (warp-uniform L1 broadcast loads)
    float s0[BPB];
    #pragma unroll
    for (int bb = 0; bb < BPB; bb++) {
        const float* c = fp + base + bb * 2560 + g * 1280;
        float acc = 0.0f;
        #pragma unroll
        for (int f = 0; f < 7; f++) acc = fmaf(__ldg(c + f), sm.C1[g][f], acc);
        s0[bb] = acc;
    }

    // ---- phase B: logits + per-warp online softmax partials (no barrier) ----
    #pragma unroll
    for (int bb = 0; bb < BPB; bb++) {
        float t = 0.0f;
        #pragma unroll
        for (int f = 0; f < 7; f++) t = fmaf(x[bb][f], sm.C2[g][f], t);
        float e = s0[bb] + t;
        e = e > 0.0f ? e : 0.2f * e;
        if (j == 0) e = -1e30f;                 // mask center (p -> 0)

        float m = e;
        #pragma unroll
        for (int o = 16; o; o >>= 1) m = fmaxf(m, __shfl_xor_sync(0xffffffffu, m, o));
        float p = __expf(e - m);
        float z = p;
        #pragma unroll
        for (int o = 16; o; o >>= 1) z += __shfl_xor_sync(0xffffffffu, z, o);
        #pragma unroll
        for (int f = 0; f < 7; f++) {
            float v = p * x[bb][f];
            #pragma unroll
            for (int o = 16; o; o >>= 1) v += __shfl_xor_sync(0xffffffffu, v, o);
            if (lane == 0) sm.Yp[bb][w][f] = v;
        }
        if (lane == 0) { sm.Mp[bb][w] = m; sm.Zp[bb][w] = z; }
        if (j == 0) {
            #pragma unroll
            for (int f = 0; f < 7; f++) sm.X0[bb][g][f] = x[bb][f];
        }
    }
    __syncthreads();

    // ---- phase C: combine 4 warp partials per (batch, graph) ----
    if (tid < BPB * 14) {
        int bb = tid / 14, rem = tid % 14;
        int gg = rem / 7, f = rem % 7;
        int wb = gg * 4;
        float m0 = sm.Mp[bb][wb], m1 = sm.Mp[bb][wb + 1];
        float m2 = sm.Mp[bb][wb + 2], m3 = sm.Mp[bb][wb + 3];
        float m = fmaxf(fmaxf(m0, m1), fmaxf(m2, m3));
        float e0 = __expf(m0 - m), e1 = __expf(m1 - m);
        float e2 = __expf(m2 - m), e3 = __expf(m3 - m);
        float Z = sm.Zp[bb][wb] * e0 + sm.Zp[bb][wb + 1] * e1
                + sm.Zp[bb][wb + 2] * e2 + sm.Zp[bb][wb + 3] * e3;
        float Y = sm.Yp[bb][wb][f] * e0 + sm.Yp[bb][wb + 1][f] * e1
                + sm.Yp[bb][wb + 2][f] * e2 + sm.Yp[bb][wb + 3][f] * e3;
        sm.Y[bb][gg][f] = Y / Z;
    }
    __syncthreads();

    // ---- phase D: Wv = elu(x0 @ W1) + 127 * elu(Y @ W1) (512 items / 256 thr) ----
    #pragma unroll
    for (int r = 0; r < 2; r++) {
        int item = tid + r * 256;
        int bb = item >> 7, gg = (item >> 6) & 1, k = item & 63;
        float c = 0.0f, l = 0.0f;
        #pragma unroll
        for (int f = 0; f < 7; f++) {
            float w1 = sm.W1[gg][f][k];
            c = fmaf(sm.Y[bb][gg][f],  w1, c);
            l = fmaf(sm.X0[bb][gg][f], w1, l);
        }
        sm.Wv[bb][gg][k] = eluf(l) + 127.0f * eluf(c);
    }
    __syncthreads();

    // ---- phase E: G[b][m] = sum_k uW2[k][m]*Wv[b][0][k] + dW2[k][m]*Wv[b][1][k]
    {
        int m = tid & 63;
        int b = tid >> 6;
        float acc = 0.0f;
        #pragma unroll 4
        for (int k = 0; k < HID; k++) {
            float wu = __ldg(&uW2[k * HID + m]);
            float wd = __ldg(&dW2[k * HID + m]);
            acc = fmaf(wu, sm.Wv[b][0][k], acc);
            acc = fmaf(wd, sm.Wv[b][1][k], acc);
        }
        sm.G[b][m] = acc;
    }
    __syncthreads();

    // ---- phase F: out = clip(relu(G @ fc2W + b), 0, 10) ----
    if (tid < BPB * TAU) {
        int b = tid / TAU, t = tid - b * TAU;
        float acc = __ldg(&fc2b[t]);
        #pragma unroll 4
        for (int m = 0; m < HID; m++)
            acc = fmaf(sm.G[b][m], __ldg(&fc2W[m * TAU + t]), acc);
        acc = fminf(fmaxf(acc, 0.0f), 10.0f);
        out[((long long)blockIdx.x * BPB + b) * TAU + t] = acc;
    }
}

extern "C" void kernel_launch(void* const* d_in, const int* in_sizes, int n_in,
                              void* d_out, int out_size)
{
    const float* fp    = (const float*)d_in[0];
    const float* uW1   = (const float*)d_in[1];
    const float* uA    = (const float*)d_in[2];
    const float* uW2   = (const float*)d_in[3];
    // d_in[4] = u_out_a : provably unused (singleton/uniform layer-2 softmax)
    const float* dW1   = (const float*)d_in[5];
    const float* dA    = (const float*)d_in[6];
    const float* dW2   = (const float*)d_in[7];
    // d_in[8] = d_out_a : unused
    const float* fc2W  = (const float*)d_in[9];
    const float* fc2b  = (const float*)d_in[10];
    float* out = (float*)d_out;

    gat_star_kernel<<<NGRID, 256>>>(fp, uW1, uA, uW2, dW1, dA, dW2, fc2W, fc2b, out);
}

// round 3
// speedup vs baseline: 1.3321x; 1.2071x over previous
#include <cuda_runtime.h>
#include <math.h>

#define NB    2048
#define BPB   4            // batches per block
#define NGRID (NB / BPB)   // 512
#define HID   64
#define TAU   22

__device__ __forceinline__ float eluf(float x) { return x > 0.0f ? x : (__expf(x) - 1.0f); }

__global__ void __launch_bounds__(256, 4) gat_star_kernel(
    const float* __restrict__ fp,
    const float* __restrict__ uW1, const float* __restrict__ uA,
    const float* __restrict__ uW2,
    const float* __restrict__ dW1, const float* __restrict__ dA,
    const float* __restrict__ dW2,
    const float* __restrict__ fc2W, const float* __restrict__ fc2b,
    float* __restrict__ out)
{
    __shared__ float W1s[2][7][HID];     // 3584 B
    __shared__ float C1s[2][7], C2s[2][7];
    __shared__ float W2s[2][HID][HID];   // 32768 B
    __shared__ float F2s[HID][TAU];      // 5632 B
    __shared__ float fbs[TAU];
    __shared__ float Wvs[8][HID];        // per-warp h-vector
    __shared__ float Gp[8][HID];         // per-warp W2 output

    const int tid = threadIdx.x;

    // ---- stage all weights into shared ----
    for (int i = tid; i < 7 * HID; i += 256) {
        ((float*)W1s)[i]           = uW1[i];
        ((float*)W1s)[7 * HID + i] = dW1[i];
    }
    {
        const float4* su = (const float4*)uW2;
        const float4* sd = (const float4*)dW2;
        float4* dst = (float4*)W2s;
        for (int i = tid; i < 1024; i += 256) {   // 4096 floats each
            dst[i]        = su[i];
            dst[1024 + i] = sd[i];
        }
    }
    for (int i = tid; i < HID * TAU; i += 256) ((float*)F2s)[i] = fc2W[i];
    if (tid < TAU) fbs[tid] = fc2b[tid];
    __syncthreads();

    // C1[g][f] = W1[g][f][:]·a[:64], C2 with a[64:]
    if (tid < 28) {
        int g = tid / 14, rem = tid % 14;
        int which = rem / 7, f = rem % 7;
        const float* a = (g == 0 ? uA : dA) + which * HID;
        float acc = 0.0f;
        #pragma unroll
        for (int k = 0; k < HID; k++) acc = fmaf(W1s[g][f][k], a[k], acc);
        if (which == 0) C1s[g][f] = acc; else C2s[g][f] = acc;
    }
    __syncthreads();

    // ---- one warp per (batch, graph) ----
    const int w    = tid >> 5;
    const int lane = tid & 31;
    const int unit = blockIdx.x * 8 + w;
    const int b    = unit >> 1;      // batch within NB
    const int g    = unit & 1;       // 0 = up, 1 = down

    const float* bp = fp + (long long)b * 2560 + g * 1280;

    // lane owns nodes {lane, lane+32, lane+64, lane+96}
    float x[4][7];
    #pragma unroll
    for (int n = 0; n < 4; n++) {
        const float* r = bp + (n * 32 + lane) * 10;   // 40B-aligned -> float2 ok
        float2 p0 = *(const float2*)(r);
        float2 p1 = *(const float2*)(r + 2);
        float2 p2 = *(const float2*)(r + 4);
        x[n][0] = p0.x; x[n][1] = p0.y;
        x[n][2] = p1.x; x[n][3] = p1.y;
        x[n][4] = p2.x; x[n][5] = p2.y;
        x[n][6] = __ldg(r + 6);
    }

    // target logits t_n = x_n · C2 ; lane0's node0 source logit s0 = x0 · C1
    float s0l = 0.0f;
    #pragma unroll
    for (int f = 0; f < 7; f++) s0l = fmaf(x[0][f], C1s[g][f], s0l);
    const float s0 = __shfl_sync(0xffffffffu, s0l, 0);

    float e[4];
    #pragma unroll
    for (int n = 0; n < 4; n++) {
        float t = 0.0f;
        #pragma unroll
        for (int f = 0; f < 7; f++) t = fmaf(x[n][f], C2s[g][f], t);
        float v = s0 + t;
        e[n] = v > 0.0f ? v : 0.2f * v;
    }
    if (lane == 0) e[0] = -1e30f;    // mask center

    // softmax over 128 values (4 per lane)
    float m = fmaxf(fmaxf(e[0], e[1]), fmaxf(e[2], e[3]));
    #pragma unroll
    for (int o = 16; o; o >>= 1) m = fmaxf(m, __shfl_xor_sync(0xffffffffu, m, o));
    float p[4], z = 0.0f;
    #pragma unroll
    for (int n = 0; n < 4; n++) { p[n] = __expf(e[n] - m); z += p[n]; }
    #pragma unroll
    for (int o = 16; o; o >>= 1) z += __shfl_xor_sync(0xffffffffu, z, o);
    const float zi = 1.0f / z;

    // Y[f] = sum_j alpha_j x_j[f]  (xor-reduce -> all lanes hold full Y)
    float Y[7];
    #pragma unroll
    for (int f = 0; f < 7; f++) {
        float v = p[0] * x[0][f] + p[1] * x[1][f] + p[2] * x[2][f] + p[3] * x[3][f];
        #pragma unroll
        for (int o = 16; o; o >>= 1) v += __shfl_xor_sync(0xffffffffu, v, o);
        Y[f] = v * zi;
    }
    // center features broadcast from lane 0
    float x0[7];
    #pragma unroll
    for (int f = 0; f < 7; f++) x0[f] = __shfl_sync(0xffffffffu, x[0][f], 0);

    // Wv[k] = elu(x0·W1[:,k]) + 127*elu(Y·W1[:,k])
    #pragma unroll
    for (int r = 0; r < 2; r++) {
        int k = lane + 32 * r;
        float c = 0.0f, l = 0.0f;
        #pragma unroll
        for (int f = 0; f < 7; f++) {
            float w1 = W1s[g][f][k];
            c = fmaf(Y[f],  w1, c);
            l = fmaf(x0[f], w1, l);
        }
        Wvs[w][k] = eluf(l) + 127.0f * eluf(c);
    }
    __syncwarp();

    // Gp[w][m] = sum_k W2[g][k][m] * Wv[k]   (conflict-free LDS, Wv broadcast)
    {
        float a0 = 0.0f, a1 = 0.0f;
        #pragma unroll 8
        for (int k = 0; k < HID; k++) {
            float wv = Wvs[w][k];
            a0 = fmaf(W2s[g][k][lane],      wv, a0);
            a1 = fmaf(W2s[g][k][lane + 32], wv, a1);
        }
        Gp[w][lane]      = a0;
        Gp[w][lane + 32] = a1;
    }
    __syncthreads();

    // fc2: out = clip(relu((Gu+Gd) @ F2 + b), 0, 10)
    if (tid < BPB * TAU) {
        int b2 = tid / TAU, t = tid - b2 * TAU;
        float acc = fbs[t];
        #pragma unroll 8
        for (int mm = 0; mm < HID; mm++)
            acc = fmaf(Gp[2 * b2][mm] + Gp[2 * b2 + 1][mm], F2s[mm][t], acc);
        acc = fminf(fmaxf(acc, 0.0f), 10.0f);
        out[((long long)blockIdx.x * BPB + b2) * TAU + t] = acc;
    }
}

extern "C" void kernel_launch(void* const* d_in, const int* in_sizes, int n_in,
                              void* d_out, int out_size)
{
    const float* fp    = (const float*)d_in[0];
    const float* uW1   = (const float*)d_in[1];
    const float* uA    = (const float*)d_in[2];
    const float* uW2   = (const float*)d_in[3];
    // d_in[4] = u_out_a : provably unused (singleton/uniform layer-2 softmax)
    const float* dW1   = (const float*)d_in[5];
    const float* dA    = (const float*)d_in[6];
    const float* dW2   = (const float*)d_in[7];
    // d_in[8] = d_out_a : unused
    const float* fc2W  = (const float*)d_in[9];
    const float* fc2b  = (const float*)d_in[10];
    float* out = (float*)d_out;

    gat_star_kernel<<<NGRID, 256>>>(fp, uW1, uA, uW2, dW1, dA, dW2, fc2W, fc2b, out);
}

// round 4
// speedup vs baseline: 1.3837x; 1.0388x over previous
#include <cuda_runtime.h>
#include <math.h>

#define NB    2048
#define BPB   4            // batches per block
#define NGRID (NB / BPB)   // 512
#define HID   64
#define TAU   22

__device__ __forceinline__ float eluf(float x) { return x > 0.0f ? x : (__expf(x) - 1.0f); }

__global__ void __launch_bounds__(256, 4) gat_star_kernel(
    const float* __restrict__ fp,
    const float* __restrict__ uW1, const float* __restrict__ uA,
    const float* __restrict__ uW2,
    const float* __restrict__ dW1, const float* __restrict__ dA,
    const float* __restrict__ dW2,
    const float* __restrict__ fc2W, const float* __restrict__ fc2b,
    float* __restrict__ out)
{
    __shared__ float feat[8][1280];      // 40960 B : per-warp graph staging
    __shared__ float W1s[2][7][HID];     //  3584 B
    __shared__ float C1s[2][7], C2s[2][7];
    __shared__ float Wvs[8][HID];        //  2048 B
    __shared__ float Gs[BPB][HID];       //  1024 B   total ~47.8 KB

    const int tid  = threadIdx.x;
    const int w    = tid >> 5;
    const int lane = tid & 31;

    // ---- per-warp coalesced feature staging (no block barrier needed) ----
    const int  unit = blockIdx.x * 8 + w;
    const int  b    = unit >> 1;     // batch index
    const int  g    = unit & 1;      // 0 = up-graph, 1 = down-graph
    {
        const float4* src = (const float4*)(fp + (long long)b * 2560 + g * 1280);
        float4* dst = (float4*)feat[w];
        #pragma unroll
        for (int i = 0; i < 10; i++)
            dst[i * 32 + lane] = src[i * 32 + lane];   // 10 x LDG.128, 1 wavefront each
    }

    // ---- stage W1, compute logit coefficient vectors ----
    for (int i = tid; i < 7 * HID; i += 256) {
        ((float*)W1s)[i]           = uW1[i];
        ((float*)W1s)[7 * HID + i] = dW1[i];
    }
    __syncthreads();
    if (tid < 28) {
        int gg = tid / 14, rem = tid % 14;
        int which = rem / 7, f = rem % 7;
        const float* a = (gg == 0 ? uA : dA) + which * HID;
        float acc = 0.0f;
        #pragma unroll
        for (int k = 0; k < HID; k++) acc = fmaf(W1s[gg][f][k], a[k], acc);
        if (which == 0) C1s[gg][f] = acc; else C2s[gg][f] = acc;
    }
    __syncthreads();   // C1/C2 visible; feat[w] already visible to own warp

    // ---- per-warp: read 4 owned nodes from smem ----
    float x[4][7];
    #pragma unroll
    for (int n = 0; n < 4; n++) {
        const float* r = &feat[w][(n * 32 + lane) * 10];
        float2 p0 = *(const float2*)(r);       // 8B-aligned (10*4*j even)
        float2 p1 = *(const float2*)(r + 2);
        float2 p2 = *(const float2*)(r + 4);
        x[n][0] = p0.x; x[n][1] = p0.y;
        x[n][2] = p1.x; x[n][3] = p1.y;
        x[n][4] = p2.x; x[n][5] = p2.y;
        x[n][6] = r[6];
    }

    // center source logit (lane 0 owns node 0)
    float s0l = 0.0f;
    #pragma unroll
    for (int f = 0; f < 7; f++) s0l = fmaf(x[0][f], C1s[g][f], s0l);
    const float s0 = __shfl_sync(0xffffffffu, s0l, 0);

    float e[4];
    #pragma unroll
    for (int n = 0; n < 4; n++) {
        float t = 0.0f;
        #pragma unroll
        for (int f = 0; f < 7; f++) t = fmaf(x[n][f], C2s[g][f], t);
        float v = s0 + t;
        e[n] = v > 0.0f ? v : 0.2f * v;
    }
    if (lane == 0) e[0] = -1e30f;            // mask center node

    // softmax over the 128 logits (4 per lane)
    float m = fmaxf(fmaxf(e[0], e[1]), fmaxf(e[2], e[3]));
    #pragma unroll
    for (int o = 16; o; o >>= 1) m = fmaxf(m, __shfl_xor_sync(0xffffffffu, m, o));
    float p[4], z = 0.0f;
    #pragma unroll
    for (int n = 0; n < 4; n++) { p[n] = __expf(e[n] - m); z += p[n]; }
    #pragma unroll
    for (int o = 16; o; o >>= 1) z += __shfl_xor_sync(0xffffffffu, z, o);
    const float zi = 1.0f / z;

    // Y[f] = sum_j alpha_j x_j[f]
    float Y[7];
    #pragma unroll
    for (int f = 0; f < 7; f++) {
        float v = p[0] * x[0][f] + p[1] * x[1][f] + p[2] * x[2][f] + p[3] * x[3][f];
        #pragma unroll
        for (int o = 16; o; o >>= 1) v += __shfl_xor_sync(0xffffffffu, v, o);
        Y[f] = v * zi;
    }
    float x0[7];
    #pragma unroll
    for (int f = 0; f < 7; f++) x0[f] = __shfl_sync(0xffffffffu, x[0][f], 0);

    // Wv[k] = elu(x0.W1[:,k]) + 127 * elu(Y.W1[:,k])
    #pragma unroll
    for (int r = 0; r < 2; r++) {
        int k = lane + 32 * r;
        float c = 0.0f, l = 0.0f;
        #pragma unroll
        for (int f = 0; f < 7; f++) {
            float w1 = W1s[g][f][k];
            c = fmaf(Y[f],  w1, c);
            l = fmaf(x0[f], w1, l);
        }
        Wvs[w][k] = eluf(l) + 127.0f * eluf(c);
    }
    __syncthreads();

    // ---- block-cooperative W2 matvec (W2 stays in L1/L2, all warps share lines)
    {
        int mm = tid & 63;
        int bb = tid >> 6;       // 0..3
        float acc = 0.0f;
        #pragma unroll 8
        for (int k = 0; k < HID; k++) {
            acc = fmaf(__ldg(&uW2[k * HID + mm]), Wvs[2 * bb][k],     acc);
            acc = fmaf(__ldg(&dW2[k * HID + mm]), Wvs[2 * bb + 1][k], acc);
        }
        Gs[bb][mm] = acc;
    }
    __syncthreads();

    // ---- fc2 head: out = clip(relu(G @ fc2W + b), 0, 10) ----
    if (tid < BPB * TAU) {
        int b2 = tid / TAU, t = tid - b2 * TAU;
        float acc = __ldg(&fc2b[t]);
        #pragma unroll 8
        for (int mm = 0; mm < HID; mm++)
            acc = fmaf(Gs[b2][mm], __ldg(&fc2W[mm * TAU + t]), acc);
        acc = fminf(fmaxf(acc, 0.0f), 10.0f);
        out[((long long)blockIdx.x * BPB + b2) * TAU + t] = acc;
    }
}

extern "C" void kernel_launch(void* const* d_in, const int* in_sizes, int n_in,
                              void* d_out, int out_size)
{
    const float* fp    = (const float*)d_in[0];
    const float* uW1   = (const float*)d_in[1];
    const float* uA    = (const float*)d_in[2];
    const float* uW2   = (const float*)d_in[3];
    // d_in[4] = u_out_a : provably unused (singleton/uniform layer-2 softmax)
    const float* dW1   = (const float*)d_in[5];
    const float* dA    = (const float*)d_in[6];
    const float* dW2   = (const float*)d_in[7];
    // d_in[8] = d_out_a : unused
    const float* fc2W  = (const float*)d_in[9];
    const float* fc2b  = (const float*)d_in[10];
    float* out = (float*)d_out;

    gat_star_kernel<<<NGRID, 256>>>(fp, uW1, uA, uW2, dW1, dA, dW2, fc2W, fc2b, out);
}